// round 1
// baseline (speedup 1.0000x reference)
#include <cuda_runtime.h>
#include <math.h>

#define NB 30

// ---------------- device scratch (no allocations allowed) ----------------
__device__ unsigned int g_hist[32][NB * NB];   // 32 2-D histograms (u cols 0-15, s cols 16-31)
__device__ unsigned int g_minmax[33][2];       // [col][0]=min key, [col][1]=max key; [32] = y_pred
__device__ double g_l1sum;
__device__ double g_mi_hist;
__device__ double g_mi_us;

// order-preserving float<->uint encoding for atomicMin/Max
static __device__ __forceinline__ unsigned fenc(float f) {
    unsigned u = __float_as_uint(f);
    return (u & 0x80000000u) ? ~u : (u | 0x80000000u);
}
static __device__ __forceinline__ float fdec(unsigned u) {
    return __uint_as_float((u & 0x80000000u) ? (u ^ 0x80000000u) : ~u);
}

// edges[j] = mn + j*delta, computed exactly like jnp.linspace (mul then add, f32 rn, no fma)
static __device__ __forceinline__ float edge_at(float mn, float delta, int j) {
    return __fadd_rn(mn, __fmul_rn((float)j, delta));
}

// searchsorted(edges[0..30], v, 'right') - 1, clipped to [0,29]  (31 edges, delta=(mx-mn)/30)
static __device__ __forceinline__ int bin30(float v, float mn, float delta, float inv) {
    int j = (int)((v - mn) * inv);
    j = j < 0 ? 0 : (j > 30 ? 30 : j);
    while (j < 30 && edge_at(mn, delta, j + 1) <= v) j++;
    while (j > 0 && edge_at(mn, delta, j) > v) j--;
    return j > 29 ? 29 : j;
}

// ---------------- init ----------------
__global__ void k_init() {
    int tid = blockIdx.x * blockDim.x + threadIdx.x;
    int total = 32 * NB * NB;
    unsigned* h = (unsigned*)g_hist;
    for (int i = tid; i < total; i += gridDim.x * blockDim.x) h[i] = 0u;
    if (tid < 33) { g_minmax[tid][0] = 0xFFFFFFFFu; g_minmax[tid][1] = 0u; }
    if (tid == 0) { g_l1sum = 0.0; g_mi_hist = 0.0; g_mi_us = 0.0; }
}

// ---------------- per-column min/max over u_vec (y==0) or s_vec (y==1) ----------------
__global__ void __launch_bounds__(256) k_minmax(const float* __restrict__ u,
                                                const float* __restrict__ s, int n) {
    const float* a = blockIdx.y ? s : u;
    int base = blockIdx.y ? 16 : 0;
    float mn[16], mx[16];
#pragma unroll
    for (int c = 0; c < 16; c++) { mn[c] = __int_as_float(0x7F800000); mx[c] = __int_as_float(0xFF800000); }
    int stride = gridDim.x * blockDim.x;
    for (int r = blockIdx.x * blockDim.x + threadIdx.x; r < n; r += stride) {
        const float4* p = (const float4*)(a + (size_t)r * 16);
        float v[16];
        float4 t;
        t = p[0]; v[0] = t.x; v[1] = t.y; v[2]  = t.z; v[3]  = t.w;
        t = p[1]; v[4] = t.x; v[5] = t.y; v[6]  = t.z; v[7]  = t.w;
        t = p[2]; v[8] = t.x; v[9] = t.y; v[10] = t.z; v[11] = t.w;
        t = p[3]; v[12] = t.x; v[13] = t.y; v[14] = t.z; v[15] = t.w;
#pragma unroll
        for (int c = 0; c < 16; c++) { mn[c] = fminf(mn[c], v[c]); mx[c] = fmaxf(mx[c], v[c]); }
    }
    __shared__ unsigned smn[16], smx[16];
    if (threadIdx.x < 16) { smn[threadIdx.x] = 0xFFFFFFFFu; smx[threadIdx.x] = 0u; }
    __syncthreads();
#pragma unroll
    for (int c = 0; c < 16; c++) {
        atomicMin(&smn[c], fenc(mn[c]));
        atomicMax(&smx[c], fenc(mx[c]));
    }
    __syncthreads();
    if (threadIdx.x < 16) {
        atomicMin(&g_minmax[base + threadIdx.x][0], smn[threadIdx.x]);
        atomicMax(&g_minmax[base + threadIdx.x][1], smx[threadIdx.x]);
    }
}

// ---------------- y_pred min/max + L1 sum ----------------
__global__ void __launch_bounds__(256) k_ypass(const float* __restrict__ yt,
                                               const float* __restrict__ yp, int n) {
    float mn = __int_as_float(0x7F800000), mx = __int_as_float(0xFF800000);
    double acc = 0.0;
    int stride = gridDim.x * blockDim.x;
    for (int i = blockIdx.x * blockDim.x + threadIdx.x; i < n; i += stride) {
        float v = yp[i];
        mn = fminf(mn, v); mx = fmaxf(mx, v);
        acc += (double)fabsf(yt[i] - v);
    }
#pragma unroll
    for (int o = 16; o; o >>= 1) {
        mn = fminf(mn, __shfl_down_sync(0xFFFFFFFFu, mn, o));
        mx = fmaxf(mx, __shfl_down_sync(0xFFFFFFFFu, mx, o));
        acc += __shfl_down_sync(0xFFFFFFFFu, acc, o);
    }
    if ((threadIdx.x & 31) == 0) {
        atomicMin(&g_minmax[32][0], fenc(mn));
        atomicMax(&g_minmax[32][1], fenc(mx));
        atomicAdd(&g_l1sum, acc);
    }
}

// ---------------- 2-D histograms: smem-privatized, packed 2x16-bit ----------------
__global__ void __launch_bounds__(256) k_hist(const float* __restrict__ u,
                                              const float* __restrict__ s,
                                              const float* __restrict__ yp, int n) {
    __shared__ unsigned sh[16 * 15 * NB];  // 16 hists, [ix][iy/2] packed pairs -> 7200 words
    const float* a = blockIdx.y ? s : u;
    int hbase = blockIdx.y ? 16 : 0;
    for (int i = threadIdx.x; i < 16 * 15 * NB; i += blockDim.x) sh[i] = 0u;

    float mn[16], dl[16], inv[16];
#pragma unroll
    for (int c = 0; c < 16; c++) {
        float lo = fdec(g_minmax[hbase + c][0]);
        float hi = fdec(g_minmax[hbase + c][1]);
        mn[c] = lo;
        dl[c] = __fdiv_rn(__fsub_rn(hi, lo), 30.0f);
        inv[c] = 1.0f / dl[c];
    }
    float ymn = fdec(g_minmax[32][0]);
    float ymx = fdec(g_minmax[32][1]);
    float ydl = __fdiv_rn(__fsub_rn(ymx, ymn), 30.0f);
    float yinv = 1.0f / ydl;
    __syncthreads();

    int stride = gridDim.x * blockDim.x;
    for (int r = blockIdx.x * blockDim.x + threadIdx.x; r < n; r += stride) {
        int iy = bin30(__ldg(yp + r), ymn, ydl, yinv);
        unsigned inc = (iy & 1) ? 0x10000u : 1u;
        int yh = iy >> 1;
        const float4* p = (const float4*)(a + (size_t)r * 16);
        float v[16];
        float4 t;
        t = p[0]; v[0] = t.x; v[1] = t.y; v[2]  = t.z; v[3]  = t.w;
        t = p[1]; v[4] = t.x; v[5] = t.y; v[6]  = t.z; v[7]  = t.w;
        t = p[2]; v[8] = t.x; v[9] = t.y; v[10] = t.z; v[11] = t.w;
        t = p[3]; v[12] = t.x; v[13] = t.y; v[14] = t.z; v[15] = t.w;
#pragma unroll
        for (int c = 0; c < 16; c++) {
            int ix = bin30(v[c], mn[c], dl[c], inv[c]);
            atomicAdd(&sh[c * (15 * NB) + ix * 15 + yh], inc);
        }
    }
    __syncthreads();
    for (int w = threadIdx.x; w < 16 * 15 * NB; w += blockDim.x) {
        unsigned x = sh[w];
        if (!x) continue;
        int c = w / (15 * NB), rr = w % (15 * NB);
        int ix = rr / 15, iy2 = (rr % 15) * 2;
        unsigned lo = x & 0xFFFFu, hi = x >> 16;
        if (lo) atomicAdd(&g_hist[hbase + c][ix * NB + iy2], lo);
        if (hi) atomicAdd(&g_hist[hbase + c][ix * NB + iy2 + 1], hi);
    }
}

// ---------------- MI from each 2-D histogram ----------------
__global__ void __launch_bounds__(256) k_mifin(float n_total) {
    int h = blockIdx.x;
    const unsigned* H = g_hist[h];
    __shared__ float rs[NB], cs[NB];
    int t = threadIdx.x;
    if (t < NB) {
        unsigned ssum = 0;
        for (int j = 0; j < NB; j++) ssum += H[t * NB + j];
        rs[t] = (float)ssum;
    } else if (t >= 32 && t < 32 + NB) {
        int c = t - 32;
        unsigned ssum = 0;
        for (int i = 0; i < NB; i++) ssum += H[i * NB + c];
        cs[c] = (float)ssum;
    }
    __syncthreads();
    double acc = 0.0;
    for (int idx = t; idx < NB * NB; idx += blockDim.x) {
        int i = idx / NB, j = idx % NB;
        float cnt = (float)H[idx];
        double pxy = (cnt > 0.f) ? (double)__fdiv_rn(cnt, n_total) : 1e-10;
        double px  = (rs[i] > 0.f) ? (double)__fdiv_rn(rs[i], n_total) : 1e-10;
        double py  = (cs[j] > 0.f) ? (double)__fdiv_rn(cs[j], n_total) : 1e-10;
        acc += pxy * log(pxy / (px * py));
    }
#pragma unroll
    for (int o = 16; o; o >>= 1) acc += __shfl_down_sync(0xFFFFFFFFu, acc, o);
    __shared__ double wacc[8];
    if ((t & 31) == 0) wacc[t >> 5] = acc;
    __syncthreads();
    if (t == 0) {
        double s = 0.0;
        for (int w = 0; w < (int)blockDim.x / 32; w++) s += wacc[w];
        atomicAdd(&g_mi_hist, s);
    }
}

// ---------------- mi_us: first 16 ROWS of u_vec/s_vec, 16 elems each ----------------
static __device__ void labelize16(const float* v, int* lab) {
    float mn = v[0], mx = v[0];
#pragma unroll
    for (int d = 1; d < 16; d++) { mn = fminf(mn, v[d]); mx = fmaxf(mx, v[d]); }
    float d29 = __fdiv_rn(__fsub_rn(mx, mn), 29.0f);  // 30 edges, div = 29
    float inv = 1.0f / d29;
#pragma unroll
    for (int d = 0; d < 16; d++) {
        float x = v[d];
        int j = (int)((x - mn) * inv);
        j = j < 0 ? 0 : (j > 29 ? 29 : j);
        while (j < 29 && edge_at(mn, d29, j + 1) <= x) j++;
        while (j > 0 && edge_at(mn, d29, j) > x) j--;
        lab[d] = j + 1;  // searchsorted(edges, x, 'right'), labels 1..30
    }
}

__global__ void k_mius(const float* __restrict__ u, const float* __restrict__ s) {
    int i = threadIdx.x;
    double acc = 0.0;
    if (i < 16) {
        float uv[16], sv[16];
#pragma unroll
        for (int d = 0; d < 16; d++) { uv[d] = u[i * 16 + d]; sv[d] = s[i * 16 + d]; }
        int lu[16], ls[16];
        labelize16(uv, lu);
        labelize16(sv, ls);
        for (int j = 0; j < 16; j++) {
            int a = 0, b = 0, c = 0;
            for (int k = 0; k < 16; k++) {
                int eu = (lu[k] == lu[j]);
                int es = (ls[k] == ls[j]);
                a += eu; b += es; c += eu & es;
            }
            acc += log((double)c * 16.0 / ((double)a * (double)b));
        }
        acc *= (1.0 / 16.0);
    }
#pragma unroll
    for (int o = 16; o; o >>= 1) acc += __shfl_down_sync(0xFFFFFFFFu, acc, o);
    if (i == 0) atomicAdd(&g_mi_us, acc);
}

// ---------------- combine ----------------
__global__ void k_combine(float* out, float n) {
    out[0] = (float)(g_l1sum / (double)n + 0.1 * g_mi_hist - 0.05 * g_mi_us);
}

// ---------------- launch ----------------
extern "C" void kernel_launch(void* const* d_in, const int* in_sizes, int n_in,
                              void* d_out, int out_size) {
    const float* y_true = (const float*)d_in[0];
    const float* y_pred = (const float*)d_in[1];
    const float* u_vec  = (const float*)d_in[4];
    const float* s_vec  = (const float*)d_in[5];
    int n = in_sizes[0];

    k_init<<<64, 256>>>();
    {
        dim3 g(148, 2);
        k_minmax<<<g, 256>>>(u_vec, s_vec, n);
    }
    k_ypass<<<148, 256>>>(y_true, y_pred, n);
    {
        dim3 g(296, 2);
        k_hist<<<g, 256>>>(u_vec, s_vec, y_pred, n);
    }
    k_mifin<<<32, 256>>>((float)n);
    k_mius<<<1, 32>>>(u_vec, s_vec);
    k_combine<<<1, 1>>>((float*)d_out, (float)n);
}

// round 2
// speedup vs baseline: 1.1786x; 1.1786x over previous
#include <cuda_runtime.h>
#include <math.h>

#define NB 30

// ---------------- device scratch ----------------
__device__ unsigned int g_hist[32][NB * NB];
__device__ unsigned int g_minmax[33][2];   // [0..15]=u cols, [16..31]=s cols, [32]=y_pred
__device__ double g_l1sum;
__device__ double g_mi_hist;
__device__ double g_mi_us;
__device__ unsigned int g_done;

// order-preserving float<->uint for atomicMin/Max
static __device__ __forceinline__ unsigned fenc(float f) {
    unsigned u = __float_as_uint(f);
    return (u & 0x80000000u) ? ~u : (u | 0x80000000u);
}
static __device__ __forceinline__ float fdec(unsigned u) {
    return __uint_as_float((u & 0x80000000u) ? (u ^ 0x80000000u) : ~u);
}

// linspace edge, exactly like jnp (mul then add, f32 rn, no fma)
static __device__ __forceinline__ float edge_at(float mn, float delta, int j) {
    return __fadd_rn(mn, __fmul_rn((float)j, delta));
}

// ---------------- init ----------------
__global__ void k_init() {
    int tid = blockIdx.x * blockDim.x + threadIdx.x;
    int total = 32 * NB * NB;
    unsigned* h = (unsigned*)g_hist;
    for (int i = tid; i < total; i += gridDim.x * blockDim.x) h[i] = 0u;
    if (tid < 33) { g_minmax[tid][0] = 0xFFFFFFFFu; g_minmax[tid][1] = 0u; }
    if (tid == 0) { g_l1sum = 0.0; g_mi_hist = 0.0; g_mi_us = 0.0; g_done = 0u; }
}

// ---------------- pass 1: column min/max (y=0:u, y=1:s) + y_pred minmax + L1 (y=2) ----------------
__global__ void __launch_bounds__(256) k_pass1(const float* __restrict__ u,
                                               const float* __restrict__ s,
                                               const float* __restrict__ yt,
                                               const float* __restrict__ yp, int n) {
    int stride = gridDim.x * blockDim.x;
    if (blockIdx.y == 2) {
        float mn = __int_as_float(0x7F800000), mx = __int_as_float(0xFF800000);
        double acc = 0.0;
        for (int i = blockIdx.x * blockDim.x + threadIdx.x; i < n; i += stride) {
            float v = yp[i];
            mn = fminf(mn, v); mx = fmaxf(mx, v);
            acc += (double)fabsf(yt[i] - v);
        }
#pragma unroll
        for (int o = 16; o; o >>= 1) {
            mn = fminf(mn, __shfl_down_sync(0xFFFFFFFFu, mn, o));
            mx = fmaxf(mx, __shfl_down_sync(0xFFFFFFFFu, mx, o));
            acc += __shfl_down_sync(0xFFFFFFFFu, acc, o);
        }
        if ((threadIdx.x & 31) == 0) {
            atomicMin(&g_minmax[32][0], fenc(mn));
            atomicMax(&g_minmax[32][1], fenc(mx));
            atomicAdd(&g_l1sum, acc);
        }
        return;
    }
    const float* a = blockIdx.y ? s : u;
    int base = blockIdx.y ? 16 : 0;
    float mn[16], mx[16];
#pragma unroll
    for (int c = 0; c < 16; c++) { mn[c] = __int_as_float(0x7F800000); mx[c] = __int_as_float(0xFF800000); }
    for (int r = blockIdx.x * blockDim.x + threadIdx.x; r < n; r += stride) {
        const float4* p = (const float4*)(a + (size_t)r * 16);
        float v[16];
        float4 t;
        t = p[0]; v[0] = t.x; v[1] = t.y; v[2]  = t.z; v[3]  = t.w;
        t = p[1]; v[4] = t.x; v[5] = t.y; v[6]  = t.z; v[7]  = t.w;
        t = p[2]; v[8] = t.x; v[9] = t.y; v[10] = t.z; v[11] = t.w;
        t = p[3]; v[12] = t.x; v[13] = t.y; v[14] = t.z; v[15] = t.w;
#pragma unroll
        for (int c = 0; c < 16; c++) { mn[c] = fminf(mn[c], v[c]); mx[c] = fmaxf(mx[c], v[c]); }
    }
    __shared__ unsigned smn[16], smx[16];
    if (threadIdx.x < 16) { smn[threadIdx.x] = 0xFFFFFFFFu; smx[threadIdx.x] = 0u; }
    __syncthreads();
#pragma unroll
    for (int c = 0; c < 16; c++) {
        atomicMin(&smn[c], fenc(mn[c]));
        atomicMax(&smx[c], fenc(mx[c]));
    }
    __syncthreads();
    if (threadIdx.x < 16) {
        atomicMin(&g_minmax[base + threadIdx.x][0], smn[threadIdx.x]);
        atomicMax(&g_minmax[base + threadIdx.x][1], smx[threadIdx.x]);
    }
}

// ---------------- pass 2: 2-D histograms, fast binning, packed 2x16-bit smem ----------------
__global__ void __launch_bounds__(256, 6) k_hist(const float* __restrict__ u,
                                                 const float* __restrict__ s,
                                                 const float* __restrict__ yp, int n) {
    __shared__ unsigned sh[16 * 15 * NB];  // 7200 words = 28.8 KB
    const float* a = blockIdx.y ? s : u;
    int hbase = blockIdx.y ? 16 : 0;
    for (int i = threadIdx.x; i < 16 * 15 * NB; i += blockDim.x) sh[i] = 0u;

    float mn[16], inv[16];
#pragma unroll
    for (int c = 0; c < 16; c++) {
        float lo = fdec(g_minmax[hbase + c][0]);
        float hi = fdec(g_minmax[hbase + c][1]);
        mn[c] = lo;
        inv[c] = 1.0f / __fdiv_rn(__fsub_rn(hi, lo), 30.0f);
    }
    float ymn = fdec(g_minmax[32][0]);
    float yinv = 1.0f / __fdiv_rn(__fsub_rn(fdec(g_minmax[32][1]), ymn), 30.0f);
    __syncthreads();

    int stride = gridDim.x * blockDim.x;
    for (int r = blockIdx.x * blockDim.x + threadIdx.x; r < n; r += stride) {
        int iy = (int)((__ldg(yp + r) - ymn) * yinv);
        iy = iy < 0 ? 0 : (iy > 29 ? 29 : iy);
        unsigned inc = (iy & 1) ? 0x10000u : 1u;
        int yh = iy >> 1;
        const float4* p = (const float4*)(a + (size_t)r * 16);
        float v[16];
        float4 t;
        t = p[0]; v[0] = t.x; v[1] = t.y; v[2]  = t.z; v[3]  = t.w;
        t = p[1]; v[4] = t.x; v[5] = t.y; v[6]  = t.z; v[7]  = t.w;
        t = p[2]; v[8] = t.x; v[9] = t.y; v[10] = t.z; v[11] = t.w;
        t = p[3]; v[12] = t.x; v[13] = t.y; v[14] = t.z; v[15] = t.w;
#pragma unroll
        for (int c = 0; c < 16; c++) {
            int ix = (int)((v[c] - mn[c]) * inv[c]);
            ix = ix < 0 ? 0 : (ix > 29 ? 29 : ix);
            atomicAdd(&sh[c * (15 * NB) + ix * 15 + yh], inc);
        }
    }
    __syncthreads();
    for (int w = threadIdx.x; w < 16 * 15 * NB; w += blockDim.x) {
        unsigned x = sh[w];
        if (!x) continue;
        int c = w / (15 * NB), rr = w % (15 * NB);
        int ix = rr / 15, iy2 = (rr % 15) * 2;
        unsigned lo = x & 0xFFFFu, hi = x >> 16;
        if (lo) atomicAdd(&g_hist[hbase + c][ix * NB + iy2], lo);
        if (hi) atomicAdd(&g_hist[hbase + c][ix * NB + iy2 + 1], hi);
    }
}

// ---------------- mi_us helpers (exact binning kept: tiny sample count) ----------------
static __device__ void labelize16(const float* v, int* lab) {
    float mn = v[0], mx = v[0];
#pragma unroll
    for (int d = 1; d < 16; d++) { mn = fminf(mn, v[d]); mx = fmaxf(mx, v[d]); }
    float d29 = __fdiv_rn(__fsub_rn(mx, mn), 29.0f);  // 30 edges -> div = 29
    float inv = 1.0f / d29;
#pragma unroll
    for (int d = 0; d < 16; d++) {
        float x = v[d];
        int j = (int)((x - mn) * inv);
        j = j < 0 ? 0 : (j > 29 ? 29 : j);
        while (j < 29 && edge_at(mn, d29, j + 1) <= x) j++;
        while (j > 0 && edge_at(mn, d29, j) > x) j--;
        lab[d] = j + 1;
    }
}

// ---------------- finalize: blocks 0..31 hist MI, block 32 mi_us, last block combines ----------------
__global__ void __launch_bounds__(256) k_fin(const float* __restrict__ u,
                                             const float* __restrict__ s,
                                             float n_total, float* __restrict__ out) {
    int t = threadIdx.x;
    if (blockIdx.x < 32) {
        const unsigned* H = g_hist[blockIdx.x];
        __shared__ float rs[NB], cs[NB];
        if (t < NB) {
            unsigned ssum = 0;
            for (int j = 0; j < NB; j++) ssum += H[t * NB + j];
            rs[t] = (float)ssum;
        } else if (t >= 32 && t < 32 + NB) {
            int c = t - 32;
            unsigned ssum = 0;
            for (int i = 0; i < NB; i++) ssum += H[i * NB + c];
            cs[c] = (float)ssum;
        }
        __syncthreads();
        double acc = 0.0;
        for (int idx = t; idx < NB * NB; idx += blockDim.x) {
            int i = idx / NB, j = idx % NB;
            float cnt = (float)H[idx];
            double pxy = (cnt > 0.f) ? (double)__fdiv_rn(cnt, n_total) : 1e-10;
            double px  = (rs[i] > 0.f) ? (double)__fdiv_rn(rs[i], n_total) : 1e-10;
            double py  = (cs[j] > 0.f) ? (double)__fdiv_rn(cs[j], n_total) : 1e-10;
            acc += pxy * log(pxy / (px * py));
        }
#pragma unroll
        for (int o = 16; o; o >>= 1) acc += __shfl_down_sync(0xFFFFFFFFu, acc, o);
        __shared__ double wacc[8];
        if ((t & 31) == 0) wacc[t >> 5] = acc;
        __syncthreads();
        if (t == 0) {
            double sum = 0.0;
            for (int w = 0; w < 8; w++) sum += wacc[w];
            atomicAdd(&g_mi_hist, sum);
        }
    } else {
        // mi_us on first 16 rows of u_vec/s_vec (threads 0..15 active)
        double acc = 0.0;
        if (t < 16) {
            float uv[16], sv[16];
#pragma unroll
            for (int d = 0; d < 16; d++) { uv[d] = u[t * 16 + d]; sv[d] = s[t * 16 + d]; }
            int lu[16], ls[16];
            labelize16(uv, lu);
            labelize16(sv, ls);
            for (int j = 0; j < 16; j++) {
                int a = 0, b = 0, c = 0;
                for (int k = 0; k < 16; k++) {
                    int eu = (lu[k] == lu[j]);
                    int es = (ls[k] == ls[j]);
                    a += eu; b += es; c += eu & es;
                }
                acc += log((double)c * 16.0 / ((double)a * (double)b));
            }
            acc *= (1.0 / 16.0);
        }
        if (t < 32) {
#pragma unroll
            for (int o = 16; o; o >>= 1) acc += __shfl_down_sync(0xFFFFFFFFu, acc, o);
            if (t == 0) atomicAdd(&g_mi_us, acc);
        }
    }
    // last-block combine
    __threadfence();
    __syncthreads();
    if (t == 0) {
        unsigned ticket = atomicAdd(&g_done, 1u);
        if (ticket == 32u) {  // all 33 blocks done
            out[0] = (float)(g_l1sum / (double)n_total + 0.1 * g_mi_hist - 0.05 * g_mi_us);
        }
    }
}

// ---------------- launch ----------------
extern "C" void kernel_launch(void* const* d_in, const int* in_sizes, int n_in,
                              void* d_out, int out_size) {
    const float* y_true = (const float*)d_in[0];
    const float* y_pred = (const float*)d_in[1];
    const float* u_vec  = (const float*)d_in[4];
    const float* s_vec  = (const float*)d_in[5];
    int n = in_sizes[0];

    k_init<<<64, 256>>>();
    {
        dim3 g(296, 3);
        k_pass1<<<g, 256>>>(u_vec, s_vec, y_true, y_pred, n);
    }
    {
        dim3 g(444, 2);
        k_hist<<<g, 256>>>(u_vec, s_vec, y_pred, n);
    }
    k_fin<<<33, 256>>>(u_vec, s_vec, (float)n, (float*)d_out);
}

// round 3
// speedup vs baseline: 1.4434x; 1.2247x over previous
#include <cuda_runtime.h>
#include <math.h>

#define NB 30

// ---------------- device scratch ----------------
__device__ unsigned int g_hist[32][NB * NB];
__device__ unsigned int g_minmax[33][2];   // [0..15]=u cols, [16..31]=s cols, [32]=y_pred
__device__ double g_l1sum;
__device__ double g_mi_hist;
__device__ double g_mi_us;

// order-preserving float<->uint for atomicMin/Max
static __device__ __forceinline__ unsigned fenc(float f) {
    unsigned u = __float_as_uint(f);
    return (u & 0x80000000u) ? ~u : (u | 0x80000000u);
}
static __device__ __forceinline__ float fdec(unsigned u) {
    return __uint_as_float((u & 0x80000000u) ? (u ^ 0x80000000u) : ~u);
}

// linspace edge, exactly like jnp (mul then add, f32 rn, no fma)
static __device__ __forceinline__ float edge_at(float mn, float delta, int j) {
    return __fadd_rn(mn, __fmul_rn((float)j, delta));
}

// ---------------- init ----------------
__global__ void k_init() {
    int tid = blockIdx.x * blockDim.x + threadIdx.x;
    int total = 32 * NB * NB;
    unsigned* h = (unsigned*)g_hist;
    for (int i = tid; i < total; i += gridDim.x * blockDim.x) h[i] = 0u;
    if (tid < 33) { g_minmax[tid][0] = 0xFFFFFFFFu; g_minmax[tid][1] = 0u; }
    if (tid == 0) { g_l1sum = 0.0; g_mi_hist = 0.0; g_mi_us = 0.0; }
}

// ---------------- pass 1: column min/max (y=0:u, y=1:s) + y_pred minmax + L1 (y=2) ----------------
__global__ void __launch_bounds__(256) k_pass1(const float* __restrict__ u,
                                               const float* __restrict__ s,
                                               const float* __restrict__ yt,
                                               const float* __restrict__ yp, int n) {
    int stride = gridDim.x * blockDim.x;
    if (blockIdx.y == 2) {
        float mn = __int_as_float(0x7F800000), mx = __int_as_float(0xFF800000);
        double acc = 0.0;
        for (int i = blockIdx.x * blockDim.x + threadIdx.x; i < n; i += stride) {
            float v = yp[i];
            mn = fminf(mn, v); mx = fmaxf(mx, v);
            acc += (double)fabsf(yt[i] - v);
        }
#pragma unroll
        for (int o = 16; o; o >>= 1) {
            mn = fminf(mn, __shfl_down_sync(0xFFFFFFFFu, mn, o));
            mx = fmaxf(mx, __shfl_down_sync(0xFFFFFFFFu, mx, o));
            acc += __shfl_down_sync(0xFFFFFFFFu, acc, o);
        }
        if ((threadIdx.x & 31) == 0) {
            atomicMin(&g_minmax[32][0], fenc(mn));
            atomicMax(&g_minmax[32][1], fenc(mx));
            atomicAdd(&g_l1sum, acc);
        }
        return;
    }
    const float* a = blockIdx.y ? s : u;
    int base = blockIdx.y ? 16 : 0;
    float mn[16], mx[16];
#pragma unroll
    for (int c = 0; c < 16; c++) { mn[c] = __int_as_float(0x7F800000); mx[c] = __int_as_float(0xFF800000); }
    for (int r = blockIdx.x * blockDim.x + threadIdx.x; r < n; r += stride) {
        const float4* p = (const float4*)(a + (size_t)r * 16);
        float v[16];
        float4 t;
        t = p[0]; v[0] = t.x; v[1] = t.y; v[2]  = t.z; v[3]  = t.w;
        t = p[1]; v[4] = t.x; v[5] = t.y; v[6]  = t.z; v[7]  = t.w;
        t = p[2]; v[8] = t.x; v[9] = t.y; v[10] = t.z; v[11] = t.w;
        t = p[3]; v[12] = t.x; v[13] = t.y; v[14] = t.z; v[15] = t.w;
#pragma unroll
        for (int c = 0; c < 16; c++) { mn[c] = fminf(mn[c], v[c]); mx[c] = fmaxf(mx[c], v[c]); }
    }
    __shared__ unsigned smn[16], smx[16];
    if (threadIdx.x < 16) { smn[threadIdx.x] = 0xFFFFFFFFu; smx[threadIdx.x] = 0u; }
    __syncthreads();
#pragma unroll
    for (int c = 0; c < 16; c++) {
        atomicMin(&smn[c], fenc(mn[c]));
        atomicMax(&smx[c], fenc(mx[c]));
    }
    __syncthreads();
    if (threadIdx.x < 16) {
        atomicMin(&g_minmax[base + threadIdx.x][0], smn[threadIdx.x]);
        atomicMax(&g_minmax[base + threadIdx.x][1], smx[threadIdx.x]);
    }
}

// ---------------- pass 2: 2-D histograms, fast binning, packed 2x16-bit smem ----------------
__global__ void __launch_bounds__(256, 6) k_hist(const float* __restrict__ u,
                                                 const float* __restrict__ s,
                                                 const float* __restrict__ yp, int n) {
    __shared__ unsigned sh[16 * 15 * NB];  // 7200 words = 28.8 KB
    const float* a = blockIdx.y ? s : u;
    int hbase = blockIdx.y ? 16 : 0;
    for (int i = threadIdx.x; i < 16 * 15 * NB; i += blockDim.x) sh[i] = 0u;

    float mn[16], inv[16];
#pragma unroll
    for (int c = 0; c < 16; c++) {
        float lo = fdec(g_minmax[hbase + c][0]);
        float hi = fdec(g_minmax[hbase + c][1]);
        mn[c] = lo;
        inv[c] = 1.0f / __fdiv_rn(__fsub_rn(hi, lo), 30.0f);
    }
    float ymn = fdec(g_minmax[32][0]);
    float yinv = 1.0f / __fdiv_rn(__fsub_rn(fdec(g_minmax[32][1]), ymn), 30.0f);
    __syncthreads();

    int stride = gridDim.x * blockDim.x;
    for (int r = blockIdx.x * blockDim.x + threadIdx.x; r < n; r += stride) {
        int iy = (int)((__ldg(yp + r) - ymn) * yinv);
        iy = iy < 0 ? 0 : (iy > 29 ? 29 : iy);
        unsigned inc = (iy & 1) ? 0x10000u : 1u;
        int yh = iy >> 1;
        const float4* p = (const float4*)(a + (size_t)r * 16);
        float v[16];
        float4 t;
        t = p[0]; v[0] = t.x; v[1] = t.y; v[2]  = t.z; v[3]  = t.w;
        t = p[1]; v[4] = t.x; v[5] = t.y; v[6]  = t.z; v[7]  = t.w;
        t = p[2]; v[8] = t.x; v[9] = t.y; v[10] = t.z; v[11] = t.w;
        t = p[3]; v[12] = t.x; v[13] = t.y; v[14] = t.z; v[15] = t.w;
#pragma unroll
        for (int c = 0; c < 16; c++) {
            int ix = (int)((v[c] - mn[c]) * inv[c]);
            ix = ix < 0 ? 0 : (ix > 29 ? 29 : ix);
            atomicAdd(&sh[c * (15 * NB) + ix * 15 + yh], inc);
        }
    }
    __syncthreads();
    for (int w = threadIdx.x; w < 16 * 15 * NB; w += blockDim.x) {
        unsigned x = sh[w];
        if (!x) continue;
        int c = w / (15 * NB), rr = w % (15 * NB);
        int ix = rr / 15, iy2 = (rr % 15) * 2;
        unsigned lo = x & 0xFFFFu, hi = x >> 16;
        if (lo) atomicAdd(&g_hist[hbase + c][ix * NB + iy2], lo);
        if (hi) atomicAdd(&g_hist[hbase + c][ix * NB + iy2 + 1], hi);
    }
}

// ---------------- mi_us helpers (exact binning kept: tiny sample count) ----------------
static __device__ void labelize16(const float* v, int* lab) {
    float mn = v[0], mx = v[0];
#pragma unroll
    for (int d = 1; d < 16; d++) { mn = fminf(mn, v[d]); mx = fmaxf(mx, v[d]); }
    float d29 = __fdiv_rn(__fsub_rn(mx, mn), 29.0f);  // 30 edges -> div = 29
    float inv = 1.0f / d29;
#pragma unroll
    for (int d = 0; d < 16; d++) {
        float x = v[d];
        int j = (int)((x - mn) * inv);
        j = j < 0 ? 0 : (j > 29 ? 29 : j);
        while (j < 29 && edge_at(mn, d29, j + 1) <= x) j++;
        while (j > 0 && edge_at(mn, d29, j) > x) j--;
        lab[d] = j + 1;
    }
}

// ---------------- finalize: blocks 0..63 hist MI (2 per hist), block 64 mi_us + combine ----------------
// fp32 log math (matches the fp32 reference); double only for accumulation.
__global__ void __launch_bounds__(256) k_fin(const float* __restrict__ u,
                                             const float* __restrict__ s,
                                             float n_total, float* __restrict__ out) {
    int t = threadIdx.x;
    if (blockIdx.x < 64) {
        int h = blockIdx.x >> 1;        // histogram id
        int half = blockIdx.x & 1;      // which half of the 900 cells
        const unsigned* H = g_hist[h];
        __shared__ float rs[NB], cs[NB];
        if (t < NB) {
            unsigned ssum = 0;
#pragma unroll
            for (int j = 0; j < NB; j++) ssum += H[t * NB + j];
            rs[t] = (float)ssum;
        } else if (t >= 32 && t < 32 + NB) {
            int c = t - 32;
            unsigned ssum = 0;
#pragma unroll
            for (int i = 0; i < NB; i++) ssum += H[i * NB + c];
            cs[c] = (float)ssum;
        }
        __syncthreads();
        float inv_n = __frcp_rn(n_total);
        double acc = 0.0;
        int begin = half * 450;
        for (int idx = begin + t; idx < begin + 450; idx += blockDim.x) {
            int i = idx / NB, j = idx % NB;
            float cnt = (float)H[idx];
            float pxy = (cnt > 0.f) ? __fdiv_rn(cnt, n_total) : 1e-10f;
            float px  = (rs[i] > 0.f) ? __fdiv_rn(rs[i], n_total) : 1e-10f;
            float py  = (cs[j] > 0.f) ? __fdiv_rn(cs[j], n_total) : 1e-10f;
            acc += (double)(pxy * logf(pxy / (px * py)));
        }
        (void)inv_n;
#pragma unroll
        for (int o = 16; o; o >>= 1) acc += __shfl_down_sync(0xFFFFFFFFu, acc, o);
        __shared__ double wacc[8];
        if ((t & 31) == 0) wacc[t >> 5] = acc;
        __syncthreads();
        if (t == 0) {
            double sum = 0.0;
            for (int w = 0; w < 8; w++) sum += wacc[w];
            atomicAdd(&g_mi_hist, sum);
        }
    } else {
        // mi_us on first 16 rows of u_vec/s_vec (threads 0..15 active)
        double acc = 0.0;
        if (t < 16) {
            float uv[16], sv[16];
#pragma unroll
            for (int d = 0; d < 16; d++) { uv[d] = u[t * 16 + d]; sv[d] = s[t * 16 + d]; }
            int lu[16], ls[16];
            labelize16(uv, lu);
            labelize16(sv, ls);
            float facc = 0.f;
            for (int j = 0; j < 16; j++) {
                int a = 0, b = 0, c = 0;
#pragma unroll
                for (int k = 0; k < 16; k++) {
                    int eu = (lu[k] == lu[j]);
                    int es = (ls[k] == ls[j]);
                    a += eu; b += es; c += eu & es;
                }
                facc += logf((float)(c * 16) / (float)(a * b));
            }
            acc = (double)facc * (1.0 / 16.0);
        }
        if (t < 32) {
#pragma unroll
            for (int o = 16; o; o >>= 1) acc += __shfl_down_sync(0xFFFFFFFFu, acc, o);
            if (t == 0) atomicAdd(&g_mi_us, acc);
        }
    }
}

// ---------------- combine (tiny, separate to avoid grid-wide sync logic) ----------------
__global__ void k_combine(float* out, float n) {
    out[0] = (float)(g_l1sum / (double)n + 0.1 * g_mi_hist - 0.05 * g_mi_us);
}

// ---------------- launch ----------------
extern "C" void kernel_launch(void* const* d_in, const int* in_sizes, int n_in,
                              void* d_out, int out_size) {
    const float* y_true = (const float*)d_in[0];
    const float* y_pred = (const float*)d_in[1];
    const float* u_vec  = (const float*)d_in[4];
    const float* s_vec  = (const float*)d_in[5];
    int n = in_sizes[0];

    k_init<<<64, 256>>>();
    {
        dim3 g(296, 3);
        k_pass1<<<g, 256>>>(u_vec, s_vec, y_true, y_pred, n);
    }
    {
        dim3 g(444, 2);
        k_hist<<<g, 256>>>(u_vec, s_vec, y_pred, n);
    }
    k_fin<<<65, 256>>>(u_vec, s_vec, (float)n, (float*)d_out);
    k_combine<<<1, 1>>>((float*)d_out, (float)n);
}

// round 4
// speedup vs baseline: 1.7521x; 1.2139x over previous
#include <cuda_runtime.h>
#include <math.h>

#define NB 30
#define GRID_MAIN 444   // 3 blocks/SM on 148 SMs; launch_bounds(256,4) guarantees residency

// ---------------- device scratch ----------------
__device__ unsigned int g_hist[32][NB * NB];
__device__ unsigned int g_minmax[33][2];   // [0..15]=u cols, [16..31]=s cols, [32]=y_pred
__device__ double g_l1sum;
__device__ double g_mi_hist;
__device__ double g_mi_us;
__device__ unsigned int g_arrive;
__device__ unsigned int g_done;

// order-preserving float<->uint for atomicMin/Max
static __device__ __forceinline__ unsigned fenc(float f) {
    unsigned u = __float_as_uint(f);
    return (u & 0x80000000u) ? ~u : (u | 0x80000000u);
}
static __device__ __forceinline__ float fdec(unsigned u) {
    return __uint_as_float((u & 0x80000000u) ? (u ^ 0x80000000u) : ~u);
}
static __device__ __forceinline__ float edge_at(float mn, float delta, int j) {
    return __fadd_rn(mn, __fmul_rn((float)j, delta));
}
static __device__ __forceinline__ void load_row16(const float* a, int r, float* v) {
    const float4* p = (const float4*)(a + (size_t)r * 16);
    float4 t;
    t = p[0]; v[0]  = t.x; v[1]  = t.y; v[2]  = t.z; v[3]  = t.w;
    t = p[1]; v[4]  = t.x; v[5]  = t.y; v[6]  = t.z; v[7]  = t.w;
    t = p[2]; v[8]  = t.x; v[9]  = t.y; v[10] = t.z; v[11] = t.w;
    t = p[3]; v[12] = t.x; v[13] = t.y; v[14] = t.z; v[15] = t.w;
}

// ---------------- init ----------------
__global__ void k_init() {
    int tid = blockIdx.x * blockDim.x + threadIdx.x;
    int total = 32 * NB * NB;
    unsigned* h = (unsigned*)g_hist;
    for (int i = tid; i < total; i += gridDim.x * blockDim.x) h[i] = 0u;
    if (tid < 33) { g_minmax[tid][0] = 0xFFFFFFFFu; g_minmax[tid][1] = 0u; }
    if (tid == 0) { g_l1sum = 0.0; g_mi_hist = 0.0; g_mi_us = 0.0; g_arrive = 0u; g_done = 0u; }
}

// ---------------- fused main: phase1 min/max + L1, spin barrier, phase2 histograms ----------------
__global__ void __launch_bounds__(256, 4) k_main(const float* __restrict__ u,
                                                 const float* __restrict__ s,
                                                 const float* __restrict__ yt,
                                                 const float* __restrict__ yp, int n) {
    __shared__ unsigned sh[16 * 15 * NB];  // 7200 words = 28.8 KB (phase 2)
    __shared__ unsigned smn[16], smx[16];  // phase 1
    int bid = blockIdx.x;
    int tid = threadIdx.x;

    // ---------- phase 1 ----------
    if (bid < 384) {
        // bid 0..191: u min/max; 192..383: s min/max
        const float* a = (bid < 192) ? u : s;
        int base = (bid < 192) ? 0 : 16;
        int pb = (bid < 192) ? bid : bid - 192;
        int stride = 192 * 256;
        float mn[16], mx[16];
#pragma unroll
        for (int c = 0; c < 16; c++) { mn[c] = __int_as_float(0x7F800000); mx[c] = __int_as_float(0xFF800000); }
        for (int r = pb * 256 + tid; r < n; r += stride) {
            float v[16];
            load_row16(a, r, v);
#pragma unroll
            for (int c = 0; c < 16; c++) { mn[c] = fminf(mn[c], v[c]); mx[c] = fmaxf(mx[c], v[c]); }
        }
        if (tid < 16) { smn[tid] = 0xFFFFFFFFu; smx[tid] = 0u; }
        __syncthreads();
#pragma unroll
        for (int c = 0; c < 16; c++) {
            atomicMin(&smn[c], fenc(mn[c]));
            atomicMax(&smx[c], fenc(mx[c]));
        }
        __syncthreads();
        if (tid < 16) {
            atomicMin(&g_minmax[base + tid][0], smn[tid]);
            atomicMax(&g_minmax[base + tid][1], smx[tid]);
        }
    } else {
        // bid 384..443: y_pred min/max + L1 sum (60 blocks)
        int pb = bid - 384;
        int stride = 60 * 256;
        float mn = __int_as_float(0x7F800000), mx = __int_as_float(0xFF800000);
        double acc = 0.0;
        for (int i = pb * 256 + tid; i < n; i += stride) {
            float v = yp[i];
            mn = fminf(mn, v); mx = fmaxf(mx, v);
            acc += (double)fabsf(yt[i] - v);
        }
#pragma unroll
        for (int o = 16; o; o >>= 1) {
            mn = fminf(mn, __shfl_down_sync(0xFFFFFFFFu, mn, o));
            mx = fmaxf(mx, __shfl_down_sync(0xFFFFFFFFu, mx, o));
            acc += __shfl_down_sync(0xFFFFFFFFu, acc, o);
        }
        if ((tid & 31) == 0) {
            atomicMin(&g_minmax[32][0], fenc(mn));
            atomicMax(&g_minmax[32][1], fenc(mx));
            atomicAdd(&g_l1sum, acc);
        }
    }

    // ---------- device-wide barrier (all 444 blocks are co-resident by launch_bounds) ----------
    __threadfence();
    __syncthreads();
    if (tid == 0) {
        atomicAdd(&g_arrive, 1u);
        while (atomicAdd(&g_arrive, 0u) < GRID_MAIN) __nanosleep(64);
    }
    __syncthreads();

    // ---------- phase 2: histograms ----------
    for (int i = tid; i < 16 * 15 * NB; i += blockDim.x) sh[i] = 0u;

    const float* a = (bid < 222) ? u : s;
    int hbase = (bid < 222) ? 0 : 16;
    int pb = (bid < 222) ? bid : bid - 222;
    int stride = 222 * 256;

    float inv[16], ninv[16];  // bin = v*inv + ninv  (ninv = -mn*inv)
#pragma unroll
    for (int c = 0; c < 16; c++) {
        float lo = fdec(g_minmax[hbase + c][0]);
        float hi = fdec(g_minmax[hbase + c][1]);
        float iv = 1.0f / __fdiv_rn(__fsub_rn(hi, lo), 30.0f);
        inv[c] = iv;
        ninv[c] = -lo * iv;
    }
    float ymn = fdec(g_minmax[32][0]);
    float yiv = 1.0f / __fdiv_rn(__fsub_rn(fdec(g_minmax[32][1]), ymn), 30.0f);
    float yni = -ymn * yiv;
    __syncthreads();

    for (int r = pb * 256 + tid; r < n; r += stride) {
        int iy = (int)fmaf(__ldg(yp + r), yiv, yni);
        iy = min(max(iy, 0), 29);
        unsigned inc = (iy & 1) ? 0x10000u : 1u;
        int yh = iy >> 1;
        float v[16];
        load_row16(a, r, v);
#pragma unroll
        for (int c = 0; c < 16; c++) {
            int ix = (int)fmaf(v[c], inv[c], ninv[c]);
            ix = min(max(ix, 0), 29);
            atomicAdd(&sh[c * (15 * NB) + ix * 15 + yh], inc);
        }
    }
    __syncthreads();
    for (int w = tid; w < 16 * 15 * NB; w += blockDim.x) {
        unsigned x = sh[w];
        if (!x) continue;
        int c = w / (15 * NB), rr = w % (15 * NB);
        int ix = rr / 15, iy2 = (rr % 15) * 2;
        unsigned lo = x & 0xFFFFu, hi = x >> 16;
        if (lo) atomicAdd(&g_hist[hbase + c][ix * NB + iy2], lo);
        if (hi) atomicAdd(&g_hist[hbase + c][ix * NB + iy2 + 1], hi);
    }
}

// ---------------- mi_us labelize (exact linspace binning: only 16 samples) ----------------
static __device__ void labelize16(const float* v, int* lab) {
    float mn = v[0], mx = v[0];
#pragma unroll
    for (int d = 1; d < 16; d++) { mn = fminf(mn, v[d]); mx = fmaxf(mx, v[d]); }
    float d29 = __fdiv_rn(__fsub_rn(mx, mn), 29.0f);
    float iv = 1.0f / d29;
#pragma unroll
    for (int d = 0; d < 16; d++) {
        float x = v[d];
        int j = (int)((x - mn) * iv);
        j = j < 0 ? 0 : (j > 29 ? 29 : j);
        while (j < 29 && edge_at(mn, d29, j + 1) <= x) j++;
        while (j > 0 && edge_at(mn, d29, j) > x) j--;
        lab[d] = j + 1;
    }
}

// ---------------- finalize: 64 hist-MI blocks + 16 mi_us blocks; last block combines ----------------
__global__ void __launch_bounds__(256) k_fin(const float* __restrict__ u,
                                             const float* __restrict__ s,
                                             float n_total, float* __restrict__ out) {
    int t = threadIdx.x;
    if (blockIdx.x < 64) {
        int h = blockIdx.x >> 1;
        int half = blockIdx.x & 1;
        const unsigned* H = g_hist[h];
        __shared__ float rs[NB], cs[NB];
        if (t < NB) {
            unsigned ssum = 0;
#pragma unroll
            for (int j = 0; j < NB; j++) ssum += H[t * NB + j];
            rs[t] = (float)ssum;
        } else if (t >= 32 && t < 32 + NB) {
            int c = t - 32;
            unsigned ssum = 0;
#pragma unroll
            for (int i = 0; i < NB; i++) ssum += H[i * NB + c];
            cs[c] = (float)ssum;
        }
        __syncthreads();
        double acc = 0.0;
        int begin = half * 450;
        for (int idx = begin + t; idx < begin + 450; idx += blockDim.x) {
            int i = idx / NB, j = idx % NB;
            float cnt = (float)H[idx];
            float pxy = (cnt > 0.f) ? __fdiv_rn(cnt, n_total) : 1e-10f;
            float px  = (rs[i] > 0.f) ? __fdiv_rn(rs[i], n_total) : 1e-10f;
            float py  = (cs[j] > 0.f) ? __fdiv_rn(cs[j], n_total) : 1e-10f;
            acc += (double)(pxy * logf(pxy / (px * py)));
        }
#pragma unroll
        for (int o = 16; o; o >>= 1) acc += __shfl_down_sync(0xFFFFFFFFu, acc, o);
        __shared__ double wacc[8];
        if ((t & 31) == 0) wacc[t >> 5] = acc;
        __syncthreads();
        if (t == 0) {
            double sum = 0.0;
            for (int w = 0; w < 8; w++) sum += wacc[w];
            atomicAdd(&g_mi_hist, sum);
        }
    } else {
        // one block per row i of mi_us
        int i = blockIdx.x - 64;
        __shared__ int slu[16], sls[16];
        if (t == 0) {
            float uv[16];
#pragma unroll
            for (int d = 0; d < 16; d++) uv[d] = u[i * 16 + d];
            labelize16(uv, slu);
        } else if (t == 32) {
            float sv[16];
#pragma unroll
            for (int d = 0; d < 16; d++) sv[d] = s[i * 16 + d];
            labelize16(sv, sls);
        }
        __syncthreads();
        float term = 0.f;
        if (t < 16) {
            int lj = slu[t], sj = sls[t];
            int a = 0, b = 0, c = 0;
#pragma unroll
            for (int k = 0; k < 16; k++) {
                int eu = (slu[k] == lj);
                int es = (sls[k] == sj);
                a += eu; b += es; c += eu & es;
            }
            term = logf((float)(c * 16) / (float)(a * b));
        }
        if (t < 32) {
            double acc = (double)term;
#pragma unroll
            for (int o = 16; o; o >>= 1) acc += __shfl_down_sync(0xFFFFFFFFu, acc, o);
            if (t == 0) atomicAdd(&g_mi_us, acc * (1.0 / 16.0));
        }
    }
    // last-block combine (80 blocks total)
    __threadfence();
    __syncthreads();
    if (t == 0) {
        unsigned ticket = atomicAdd(&g_done, 1u);
        if (ticket == 79u) {
            out[0] = (float)(g_l1sum / (double)n_total + 0.1 * g_mi_hist - 0.05 * g_mi_us);
        }
    }
}

// ---------------- launch ----------------
extern "C" void kernel_launch(void* const* d_in, const int* in_sizes, int n_in,
                              void* d_out, int out_size) {
    const float* y_true = (const float*)d_in[0];
    const float* y_pred = (const float*)d_in[1];
    const float* u_vec  = (const float*)d_in[4];
    const float* s_vec  = (const float*)d_in[5];
    int n = in_sizes[0];

    k_init<<<64, 256>>>();
    k_main<<<GRID_MAIN, 256>>>(u_vec, s_vec, y_true, y_pred, n);
    k_fin<<<80, 256>>>(u_vec, s_vec, (float)n, (float*)d_out);
}